// round 12
// baseline (speedup 1.0000x reference)
#include <cuda_runtime.h>
#include <cstdint>

// Fixed problem: N=20000, D=512, 2D=1024, S=25, N_TOTAL=40000
#define MAX_N   20000
#define MAX_D   512
#define MAX_NBM 160

#define BM 128
#define BN 128
#define BKT 16
#define SMP 20   // padded smem row stride (words): conflict-free frag loads, 16B-aligned rows

// -------- scratch (static device globals; no runtime allocation) --------
__device__ float g_hin[(size_t)MAX_N * 2 * MAX_D];   // [N, 2D] concat(self, agg)
__device__ float g_h  [(size_t)MAX_N * MAX_D];       // [N, D] post relu
__device__ float g_psum  [(size_t)MAX_NBM * MAX_D];
__device__ float g_psumsq[(size_t)MAX_NBM * MAX_D];
__device__ float g_scale[MAX_D];                     // rstd*gamma
__device__ float g_shift[MAX_D];                     // beta - mu*rstd*gamma
__device__ int   g_idx64;

// -------- no-op: aligns the ncu -s 5 capture window onto k_gemm --------
__global__ void k_dummy() {}

// -------- index dtype detection (int64 vs int32): one warp, ballot --------
__global__ void k_detect(const void* neigh, long long count_elems, long long n_total) {
    const long long* p = (const long long*)neigh;
    long long n64 = count_elems / 2;
    int n = (n64 < 64) ? (int)n64 : 64;
    int lane = threadIdx.x & 31;
    int bad = 0;
    for (int i = lane; i < n; i += 32) {
        long long v = p[i];
        if (v < 0 || v >= n_total) bad = 1;
    }
    unsigned m = __ballot_sync(0xFFFFFFFFu, bad);
    if (lane == 0) g_idx64 = (m == 0u);
}

// -------- gather + mean aggregate -> g_hin --------
__global__ void k_agg(const float* __restrict__ feat,
                      const void* __restrict__ self_idx,
                      const void* __restrict__ neigh_idx,
                      int N, int S, int D) {
    int i = blockIdx.x;
    int t = threadIdx.x;
    int is64 = g_idx64;

    __shared__ int s_n[64];
    __shared__ int s_self;
    if (t < S) {
        s_n[t] = is64 ? (int)((const long long*)neigh_idx)[(size_t)i * S + t]
                      : ((const int*)neigh_idx)[(size_t)i * S + t];
    }
    if (t == 0) {
        s_self = is64 ? (int)((const long long*)self_idx)[i]
                      : ((const int*)self_idx)[i];
    }
    __syncthreads();

    float inv = 1.0f / (float)S;
    size_t base = (size_t)i * 2 * D;
    for (int c = t * 4; c < D; c += blockDim.x * 4) {
        float4 sv = *(const float4*)(feat + (size_t)s_self * D + c);
        float4 acc = make_float4(0.f, 0.f, 0.f, 0.f);
        for (int s = 0; s < S; s++) {
            float4 v = *(const float4*)(feat + (size_t)s_n[s] * D + c);
            acc.x += v.x; acc.y += v.y; acc.z += v.z; acc.w += v.w;
        }
        acc.x *= inv; acc.y *= inv; acc.z *= inv; acc.w *= inv;
        *(float4*)(g_hin + base + c)     = sv;
        *(float4*)(g_hin + base + D + c) = acc;
    }
}

// -------- TF32 helpers --------
__device__ __forceinline__ uint32_t f2tf32(float x) {
    uint32_t r;
    asm("cvt.rna.tf32.f32 %0, %1;" : "=r"(r) : "f"(x));
    return r;
}

__device__ __forceinline__ uint4 f4tf32(float4 v) {
    return make_uint4(f2tf32(v.x), f2tf32(v.y), f2tf32(v.z), f2tf32(v.w));
}

__device__ __forceinline__ void mma_tf32(float& c0, float& c1, float& c2, float& c3,
                                         uint32_t a0, uint32_t a1, uint32_t a2, uint32_t a3,
                                         uint32_t b0, uint32_t b1) {
    asm volatile("mma.sync.aligned.m16n8k8.row.col.f32.tf32.tf32.f32 "
                 "{%0,%1,%2,%3}, {%4,%5,%6,%7}, {%8,%9}, {%0,%1,%2,%3};"
                 : "+f"(c0), "+f"(c1), "+f"(c2), "+f"(c3)
                 : "r"(a0), "r"(a1), "r"(a2), "r"(a3), "r"(b0), "r"(b1));
}

// -------- GEMM: g_h = relu(g_hin @ W^T + b); per-block column partials --------
// CTA tile 128x128xK, BK=16; warps 2(M) x 4(N); warp tile 64x32; m16n8k8, pure tf32.
// tf32 conversion happens ONCE at smem-store time; mainloop is raw LDS.32 + MMA.
__global__ __launch_bounds__(256, 2)
void k_gemm(const float* __restrict__ Wmat, const float* __restrict__ bias,
            int M, int NC, int K) {
    __shared__ __align__(16) union {
        struct { uint32_t A[2][BM][SMP]; uint32_t B[2][BN][SMP]; } ml;   // 40 KB
        struct { float cs[2][BN]; float cq[2][BN]; } ep;                 //  2 KB
    } sm;

    const int tid  = threadIdx.x;
    const int warp = tid >> 5, lane = tid & 31;
    const int wm = warp >> 2, wn = warp & 3;      // 2 x 4 warp grid
    const int g  = lane >> 2, tg = lane & 3;      // mma fragment coords

    const int mb = blockIdx.x, nb = blockIdx.y;
    const int row0 = mb * BM, col0 = nb * BN;

    // global->smem loader: each thread covers rows {lrow, lrow+64} of A and B tiles
    const int lrow = tid >> 2;                    // 0..63
    const int lkq  = (tid & 3) << 2;              // 0,4,8,12
    const int ga0 = row0 + lrow, ga1 = row0 + lrow + 64;
    const bool ok0 = ga0 < M, ok1 = ga1 < M;
    const float* aptr0 = g_hin + (size_t)(ok0 ? ga0 : 0) * K + lkq;
    const float* aptr1 = g_hin + (size_t)(ok1 ? ga1 : 0) * K + lkq;
    const float* bptr0 = Wmat + (size_t)(col0 + lrow) * K + lkq;
    const float* bptr1 = Wmat + (size_t)(col0 + lrow + 64) * K + lkq;

    float c[4][4][4];   // [mt][nt][frag]
#pragma unroll
    for (int mt = 0; mt < 4; mt++)
#pragma unroll
        for (int nt = 0; nt < 4; nt++)
#pragma unroll
            for (int q = 0; q < 4; q++) c[mt][nt][q] = 0.f;

    const float4 fz = make_float4(0.f, 0.f, 0.f, 0.f);

    // prologue: tile k0=0 -> buffer 0 (convert to tf32 bits at store)
    {
        float4 a0 = ok0 ? *(const float4*)(aptr0) : fz;
        float4 a1 = ok1 ? *(const float4*)(aptr1) : fz;
        float4 b0 = *(const float4*)(bptr0);
        float4 b1 = *(const float4*)(bptr1);
        *(uint4*)&sm.ml.A[0][lrow     ][lkq] = f4tf32(a0);
        *(uint4*)&sm.ml.A[0][lrow + 64][lkq] = f4tf32(a1);
        *(uint4*)&sm.ml.B[0][lrow     ][lkq] = f4tf32(b0);
        *(uint4*)&sm.ml.B[0][lrow + 64][lkq] = f4tf32(b1);
    }
    __syncthreads();

    int buf = 0;
    for (int k0 = 0; k0 < K; k0 += BKT) {
        float4 pa0, pa1, pb0, pb1;
        const bool next = (k0 + BKT) < K;
        if (next) {
            pa0 = ok0 ? *(const float4*)(aptr0 + k0 + BKT) : fz;
            pa1 = ok1 ? *(const float4*)(aptr1 + k0 + BKT) : fz;
            pb0 = *(const float4*)(bptr0 + k0 + BKT);
            pb1 = *(const float4*)(bptr1 + k0 + BKT);
        }

#pragma unroll
        for (int kk = 0; kk < BKT; kk += 8) {
            uint32_t Ah[4][4];
#pragma unroll
            for (int mt = 0; mt < 4; mt++) {
                int m0 = wm * 64 + mt * 16;
                Ah[mt][0] = sm.ml.A[buf][m0 + g    ][kk + tg];
                Ah[mt][1] = sm.ml.A[buf][m0 + g + 8][kk + tg];
                Ah[mt][2] = sm.ml.A[buf][m0 + g    ][kk + tg + 4];
                Ah[mt][3] = sm.ml.A[buf][m0 + g + 8][kk + tg + 4];
            }
            uint32_t Bh[4][2];
#pragma unroll
            for (int nt = 0; nt < 4; nt++) {
                int n0 = wn * 32 + nt * 8;
                Bh[nt][0] = sm.ml.B[buf][n0 + g][kk + tg];
                Bh[nt][1] = sm.ml.B[buf][n0 + g][kk + tg + 4];
            }
#pragma unroll
            for (int mt = 0; mt < 4; mt++)
#pragma unroll
                for (int nt = 0; nt < 4; nt++) {
                    float* cc = c[mt][nt];
                    mma_tf32(cc[0], cc[1], cc[2], cc[3],
                             Ah[mt][0], Ah[mt][1], Ah[mt][2], Ah[mt][3],
                             Bh[nt][0], Bh[nt][1]);
                }
        }

        if (next) {
            int nb2 = buf ^ 1;
            *(uint4*)&sm.ml.A[nb2][lrow     ][lkq] = f4tf32(pa0);
            *(uint4*)&sm.ml.A[nb2][lrow + 64][lkq] = f4tf32(pa1);
            *(uint4*)&sm.ml.B[nb2][lrow     ][lkq] = f4tf32(pb0);
            *(uint4*)&sm.ml.B[nb2][lrow + 64][lkq] = f4tf32(pb1);
            __syncthreads();
            buf = nb2;
        } else {
            __syncthreads();   // protect union aliasing before epilogue smem writes
        }
    }

    // epilogue: bias + relu, store, deterministic column partials
    float bl[4][2];
#pragma unroll
    for (int nt = 0; nt < 4; nt++) {
        int cb = col0 + wn * 32 + nt * 8 + 2 * tg;
        bl[nt][0] = bias[cb];
        bl[nt][1] = bias[cb + 1];
    }

    float cs[4][2], cq[4][2];
#pragma unroll
    for (int nt = 0; nt < 4; nt++) { cs[nt][0] = cs[nt][1] = 0.f; cq[nt][0] = cq[nt][1] = 0.f; }

#pragma unroll
    for (int mt = 0; mt < 4; mt++) {
        int r0 = row0 + wm * 64 + mt * 16 + g;
        int r1 = r0 + 8;
#pragma unroll
        for (int nt = 0; nt < 4; nt++) {
            int cb = col0 + wn * 32 + nt * 8 + 2 * tg;
            if (r0 < M) {
                float v0 = fmaxf(c[mt][nt][0] + bl[nt][0], 0.f);
                float v1 = fmaxf(c[mt][nt][1] + bl[nt][1], 0.f);
                *(float2*)(g_h + (size_t)r0 * NC + cb) = make_float2(v0, v1);
                cs[nt][0] += v0; cq[nt][0] += v0 * v0;
                cs[nt][1] += v1; cq[nt][1] += v1 * v1;
            }
            if (r1 < M) {
                float v2 = fmaxf(c[mt][nt][2] + bl[nt][0], 0.f);
                float v3 = fmaxf(c[mt][nt][3] + bl[nt][1], 0.f);
                *(float2*)(g_h + (size_t)r1 * NC + cb) = make_float2(v2, v3);
                cs[nt][0] += v2; cq[nt][0] += v2 * v2;
                cs[nt][1] += v3; cq[nt][1] += v3 * v3;
            }
        }
    }

    // reduce over the g dimension (lanes sharing tg): xor masks 4, 8, 16
#pragma unroll
    for (int mask = 4; mask <= 16; mask <<= 1) {
#pragma unroll
        for (int nt = 0; nt < 4; nt++) {
            cs[nt][0] += __shfl_xor_sync(0xFFFFFFFFu, cs[nt][0], mask);
            cs[nt][1] += __shfl_xor_sync(0xFFFFFFFFu, cs[nt][1], mask);
            cq[nt][0] += __shfl_xor_sync(0xFFFFFFFFu, cq[nt][0], mask);
            cq[nt][1] += __shfl_xor_sync(0xFFFFFFFFu, cq[nt][1], mask);
        }
    }
    if (lane < 4) {   // lane == tg for these lanes
#pragma unroll
        for (int nt = 0; nt < 4; nt++) {
            int cc = wn * 32 + nt * 8 + 2 * lane;
            sm.ep.cs[wm][cc]     = cs[nt][0];
            sm.ep.cs[wm][cc + 1] = cs[nt][1];
            sm.ep.cq[wm][cc]     = cq[nt][0];
            sm.ep.cq[wm][cc + 1] = cq[nt][1];
        }
    }
    __syncthreads();
    if (tid < BN) {
        g_psum  [(size_t)mb * NC + col0 + tid] = sm.ep.cs[0][tid] + sm.ep.cs[1][tid];
        g_psumsq[(size_t)mb * NC + col0 + tid] = sm.ep.cq[0][tid] + sm.ep.cq[1][tid];
    }
}

// -------- column stats: coalesced, m-parallel; fold BN affine into (scale, shift) --------
__global__ void k_stats(const float* __restrict__ gamma, const float* __restrict__ beta,
                        int nbm, int NC, int N) {
    __shared__ float s_s[8][32];
    __shared__ float s_q[8][32];
    int txc = threadIdx.x;            // 0..31 column within group
    int tym = threadIdx.y;            // 0..7  m-parallel
    int c = blockIdx.x * 32 + txc;

    float s = 0.f, q = 0.f;
    for (int m = tym; m < nbm; m += 8) {
        s += g_psum  [(size_t)m * NC + c];
        q += g_psumsq[(size_t)m * NC + c];
    }
    s_s[tym][txc] = s;
    s_q[tym][txc] = q;
    __syncthreads();
    if (tym == 0) {
#pragma unroll
        for (int m = 1; m < 8; m++) { s += s_s[m][txc]; q += s_q[m][txc]; }
        float mu  = s / (float)N;
        float var = q / (float)N - mu * mu;
        float rstd = rsqrtf(var + 1e-5f);
        float sc = rstd * gamma[c];
        g_scale[c] = sc;
        g_shift[c] = beta[c] - mu * sc;
    }
}

// -------- BN apply (y = h*scale + shift) + row L2 normalize --------
__global__ void k_final(float* __restrict__ out, int N, int NC) {
    int i = blockIdx.x;
    int t = threadIdx.x;
    int lane = t & 31, warp = t >> 5;

    __shared__ float ws[8];
    __shared__ float s_rs;

    float4 y[4];          // NC=512, blockDim=128 -> exactly 4 float4 per thread
    int nchunk = 0;

    float ss = 0.f;
    for (int c = t * 4; c < NC; c += blockDim.x * 4) {
        float4 h  = *(const float4*)(g_h + (size_t)i * NC + c);
        float4 sc = *(const float4*)(g_scale + c);
        float4 sh = *(const float4*)(g_shift + c);
        float4 v;
        v.x = fmaf(h.x, sc.x, sh.x);
        v.y = fmaf(h.y, sc.y, sh.y);
        v.z = fmaf(h.z, sc.z, sh.z);
        v.w = fmaf(h.w, sc.w, sh.w);
        if (nchunk < 4) y[nchunk] = v;
        nchunk++;
        ss += v.x * v.x + v.y * v.y + v.z * v.z + v.w * v.w;
    }
#pragma unroll
    for (int off = 16; off > 0; off >>= 1)
        ss += __shfl_xor_sync(0xFFFFFFFFu, ss, off);
    if (lane == 0) ws[warp] = ss;
    __syncthreads();
    if (t == 0) {
        float tot = 0.f;
        int nw = (blockDim.x + 31) >> 5;
        for (int w = 0; w < nw; w++) tot += ws[w];
        s_rs = 1.f / (sqrtf(tot) + 1e-6f);
    }
    __syncthreads();
    float rs = s_rs;

    int idx = 0;
    for (int c = t * 4; c < NC && idx < 4; c += blockDim.x * 4, idx++) {
        float4 v = y[idx];
        v.x *= rs; v.y *= rs; v.z *= rs; v.w *= rs;
        *(float4*)(out + (size_t)i * NC + c) = v;
    }
}

extern "C" void kernel_launch(void* const* d_in, const int* in_sizes, int n_in,
                              void* d_out, int out_size) {
    const float* feat  = (const float*)d_in[0];
    const float* W     = (const float*)d_in[1];
    const float* bias  = (const float*)d_in[2];
    const float* gamma = (const float*)d_in[3];
    const float* beta  = (const float*)d_in[4];
    const void*  selfi = d_in[5];
    const void*  neigh = d_in[6];

    int D  = in_sizes[2];                       // 512
    long long NT = (long long)in_sizes[0] / D;  // 40000
    int K  = in_sizes[1] / D;                   // 1024 (= 2D)
    int N  = in_sizes[5];                       // 20000
    int S  = in_sizes[6] / N;                   // 25
    int nbm = (N + BM - 1) / BM;                // 157

    k_detect<<<1, 32>>>(neigh, (long long)in_sizes[6], NT);   // pos 0
    k_agg<<<N, 128>>>(feat, selfi, neigh, N, S, D);           // pos 1
    k_dummy<<<1, 32>>>();                                     // pos 2 (shifts ncu window)
    dim3 gg(nbm, D / BN);
    k_gemm<<<gg, 256>>>(W, bias, N, D, K);                    // pos 3 <- ncu capture slot
    dim3 sb(32, 8);
    k_stats<<<D / 32, sb>>>(gamma, beta, nbm, D, N);          // pos 4
    k_final<<<N, 128>>>((float*)d_out, N, D);                 // pos 5
}

// round 14
// speedup vs baseline: 1.0950x; 1.0950x over previous
#include <cuda_runtime.h>
#include <cstdint>

// Fixed problem: N=20000, D=512, 2D=1024, S=25, N_TOTAL=40000
#define MAX_N   20000
#define MAX_D   512
#define MAX_NBM 160

#define BM 128
#define BN 128
#define BKT 16
#define SMP 20   // padded smem row stride (words): conflict-free frag loads, 16B-aligned rows

// -------- scratch (static device globals; no runtime allocation) --------
__device__ uint32_t g_hin[(size_t)MAX_N * 2 * MAX_D];   // [N, 2D] concat(self, agg), tf32 bits
__device__ uint32_t g_wt [(size_t)MAX_D * 2 * MAX_D];   // W as tf32 bits [D][2D]
__device__ float g_h  [(size_t)MAX_N * MAX_D];          // [N, D] post relu
__device__ float g_psum  [(size_t)MAX_NBM * MAX_D];
__device__ float g_psumsq[(size_t)MAX_NBM * MAX_D];
__device__ float g_scale[MAX_D];                        // rstd*gamma
__device__ float g_shift[MAX_D];                        // beta - mu*rstd*gamma
__device__ int   g_idx64;

// -------- TF32 helpers --------
__device__ __forceinline__ uint32_t f2tf32(float x) {
    uint32_t r;
    asm("cvt.rna.tf32.f32 %0, %1;" : "=r"(r) : "f"(x));
    return r;
}
__device__ __forceinline__ uint4 f4tf32(float4 v) {
    return make_uint4(f2tf32(v.x), f2tf32(v.y), f2tf32(v.z), f2tf32(v.w));
}

__device__ __forceinline__ void mma_tf32(float& c0, float& c1, float& c2, float& c3,
                                         uint32_t a0, uint32_t a1, uint32_t a2, uint32_t a3,
                                         uint32_t b0, uint32_t b1) {
    asm volatile("mma.sync.aligned.m16n8k8.row.col.f32.tf32.tf32.f32 "
                 "{%0,%1,%2,%3}, {%4,%5,%6,%7}, {%8,%9}, {%0,%1,%2,%3};"
                 : "+f"(c0), "+f"(c1), "+f"(c2), "+f"(c3)
                 : "r"(a0), "r"(a1), "r"(a2), "r"(a3), "r"(b0), "r"(b1));
}

// -------- cp.async helpers --------
#define CP_ASYNC16(smaddr, gptr, nbytes) \
    asm volatile("cp.async.cg.shared.global [%0], [%1], 16, %2;" \
                 :: "r"(smaddr), "l"(gptr), "r"(nbytes))
#define CP_COMMIT() asm volatile("cp.async.commit_group;" ::: "memory")
#define CP_WAIT(n)  asm volatile("cp.async.wait_group %0;" :: "n"(n) : "memory")

// -------- index dtype detection (int64 vs int32): one warp, ballot --------
__global__ void k_detect(const void* neigh, long long count_elems, long long n_total) {
    const long long* p = (const long long*)neigh;
    long long n64 = count_elems / 2;
    int n = (n64 < 64) ? (int)n64 : 64;
    int lane = threadIdx.x & 31;
    int bad = 0;
    for (int i = lane; i < n; i += 32) {
        long long v = p[i];
        if (v < 0 || v >= n_total) bad = 1;
    }
    unsigned m = __ballot_sync(0xFFFFFFFFu, bad);
    if (lane == 0) g_idx64 = (m == 0u);
}

// -------- gather + mean aggregate -> g_hin (tf32 bits) --------
__global__ void k_agg(const float* __restrict__ feat,
                      const void* __restrict__ self_idx,
                      const void* __restrict__ neigh_idx,
                      int N, int S, int D) {
    int i = blockIdx.x;
    int t = threadIdx.x;
    int is64 = g_idx64;

    __shared__ int s_n[64];
    __shared__ int s_self;
    if (t < S) {
        s_n[t] = is64 ? (int)((const long long*)neigh_idx)[(size_t)i * S + t]
                      : ((const int*)neigh_idx)[(size_t)i * S + t];
    }
    if (t == 0) {
        s_self = is64 ? (int)((const long long*)self_idx)[i]
                      : ((const int*)self_idx)[i];
    }
    __syncthreads();

    float inv = 1.0f / (float)S;
    size_t base = (size_t)i * 2 * D;
    for (int c = t * 4; c < D; c += blockDim.x * 4) {
        float4 sv = *(const float4*)(feat + (size_t)s_self * D + c);
        float4 acc = make_float4(0.f, 0.f, 0.f, 0.f);
        for (int s = 0; s < S; s++) {
            float4 v = *(const float4*)(feat + (size_t)s_n[s] * D + c);
            acc.x += v.x; acc.y += v.y; acc.z += v.z; acc.w += v.w;
        }
        acc.x *= inv; acc.y *= inv; acc.z *= inv; acc.w *= inv;
        *(uint4*)(g_hin + base + c)     = f4tf32(sv);
        *(uint4*)(g_hin + base + D + c) = f4tf32(acc);
    }
}

// -------- convert W to tf32 bits (one-shot, bandwidth-trivial) --------
__global__ void k_cvtw(const float* __restrict__ W, int total) {
    int i = (blockIdx.x * blockDim.x + threadIdx.x) * 4;
    if (i < total) {
        float4 v = *(const float4*)(W + i);
        *(uint4*)(g_wt + i) = f4tf32(v);
    }
}

// -------- GEMM: g_h = relu(g_hin @ W^T + b); per-block column partials --------
// CTA tile 128x128xK, BK=16; warps 2(M) x 4(N); warp tile 64x32; m16n8k8, pure tf32.
// Operands are pre-converted tf32 bits; smem fill via cp.async (no register staging,
// no conversions anywhere in this kernel). Mainloop = LDS.32 + MMA only.
__global__ __launch_bounds__(256, 2)
void k_gemm(const float* __restrict__ bias, int M, int NC, int K) {
    __shared__ __align__(16) union {
        struct { uint32_t A[2][BM][SMP]; uint32_t B[2][BN][SMP]; } ml;   // 40 KB
        struct { float cs[2][BN]; float cq[2][BN]; } ep;                 //  2 KB
    } sm;

    const int tid  = threadIdx.x;
    const int warp = tid >> 5, lane = tid & 31;
    const int wm = warp >> 2, wn = warp & 3;      // 2 x 4 warp grid
    const int g  = lane >> 2, tg = lane & 3;      // mma fragment coords

    const int mb = blockIdx.x, nb = blockIdx.y;
    const int row0 = mb * BM, col0 = nb * BN;

    // global->smem loader: each thread covers rows {lrow, lrow+64} of A and B tiles
    const int lrow = tid >> 2;                    // 0..63
    const int lkq  = (tid & 3) << 2;              // 0,4,8,12
    const int ga0 = row0 + lrow, ga1 = row0 + lrow + 64;
    const int na0 = (ga0 < M) ? 16 : 0;           // src-size for zfill on OOB rows
    const int na1 = (ga1 < M) ? 16 : 0;
    const uint32_t* aptr0 = g_hin + (size_t)((ga0 < M) ? ga0 : 0) * K + lkq;
    const uint32_t* aptr1 = g_hin + (size_t)((ga1 < M) ? ga1 : 0) * K + lkq;
    const uint32_t* bptr0 = g_wt + (size_t)(col0 + lrow) * K + lkq;
    const uint32_t* bptr1 = g_wt + (size_t)(col0 + lrow + 64) * K + lkq;

    // per-thread smem dst addresses for the two buffers
    uint32_t sA0[2], sA1[2], sB0[2], sB1[2];
#pragma unroll
    for (int b = 0; b < 2; b++) {
        sA0[b] = (uint32_t)__cvta_generic_to_shared(&sm.ml.A[b][lrow     ][lkq]);
        sA1[b] = (uint32_t)__cvta_generic_to_shared(&sm.ml.A[b][lrow + 64][lkq]);
        sB0[b] = (uint32_t)__cvta_generic_to_shared(&sm.ml.B[b][lrow     ][lkq]);
        sB1[b] = (uint32_t)__cvta_generic_to_shared(&sm.ml.B[b][lrow + 64][lkq]);
    }

    float c[4][4][4];   // [mt][nt][frag]
#pragma unroll
    for (int mt = 0; mt < 4; mt++)
#pragma unroll
        for (int nt = 0; nt < 4; nt++)
#pragma unroll
            for (int q = 0; q < 4; q++) c[mt][nt][q] = 0.f;

    // prologue: issue stages for k0=0 (buf0) and k0=BKT (buf1)
    CP_ASYNC16(sA0[0], aptr0,       na0);
    CP_ASYNC16(sA1[0], aptr1,       na1);
    CP_ASYNC16(sB0[0], bptr0,       16);
    CP_ASYNC16(sB1[0], bptr1,       16);
    CP_COMMIT();
    CP_ASYNC16(sA0[1], aptr0 + BKT, na0);
    CP_ASYNC16(sA1[1], aptr1 + BKT, na1);
    CP_ASYNC16(sB0[1], bptr0 + BKT, 16);
    CP_ASYNC16(sB1[1], bptr1 + BKT, 16);
    CP_COMMIT();
    CP_WAIT(1);          // buf0 ready
    __syncthreads();

    int buf = 0;
    for (int k0 = 0; k0 < K; k0 += BKT) {
        // ---- compute on buf ----
#pragma unroll
        for (int kk = 0; kk < BKT; kk += 8) {
            uint32_t Ah[4][4];
#pragma unroll
            for (int mt = 0; mt < 4; mt++) {
                int m0 = wm * 64 + mt * 16;
                Ah[mt][0] = sm.ml.A[buf][m0 + g    ][kk + tg];
                Ah[mt][1] = sm.ml.A[buf][m0 + g + 8][kk + tg];
                Ah[mt][2] = sm.ml.A[buf][m0 + g    ][kk + tg + 4];
                Ah[mt][3] = sm.ml.A[buf][m0 + g + 8][kk + tg + 4];
            }
            uint32_t Bh[4][2];
#pragma unroll
            for (int nt = 0; nt < 4; nt++) {
                int n0 = wn * 32 + nt * 8;
                Bh[nt][0] = sm.ml.B[buf][n0 + g][kk + tg];
                Bh[nt][1] = sm.ml.B[buf][n0 + g][kk + tg + 4];
            }
#pragma unroll
            for (int mt = 0; mt < 4; mt++)
#pragma unroll
                for (int nt = 0; nt < 4; nt++) {
                    float* cc = c[mt][nt];
                    mma_tf32(cc[0], cc[1], cc[2], cc[3],
                             Ah[mt][0], Ah[mt][1], Ah[mt][2], Ah[mt][3],
                             Bh[nt][0], Bh[nt][1]);
                }
        }
        __syncthreads();   // all warps done reading buf before it is refilled

        if (k0 + 2 * BKT < K) {
            int kn = k0 + 2 * BKT;
            CP_ASYNC16(sA0[buf], aptr0 + kn, na0);
            CP_ASYNC16(sA1[buf], aptr1 + kn, na1);
            CP_ASYNC16(sB0[buf], bptr0 + kn, 16);
            CP_ASYNC16(sB1[buf], bptr1 + kn, 16);
            CP_COMMIT();
            CP_WAIT(1);    // next buf (issued earlier) complete
        } else {
            CP_WAIT(0);    // tail: drain everything
        }
        __syncthreads();
        buf ^= 1;
    }

    // epilogue: bias + relu, store, deterministic column partials
    float bl[4][2];
#pragma unroll
    for (int nt = 0; nt < 4; nt++) {
        int cb = col0 + wn * 32 + nt * 8 + 2 * tg;
        bl[nt][0] = bias[cb];
        bl[nt][1] = bias[cb + 1];
    }

    float cs[4][2], cq[4][2];
#pragma unroll
    for (int nt = 0; nt < 4; nt++) { cs[nt][0] = cs[nt][1] = 0.f; cq[nt][0] = cq[nt][1] = 0.f; }

#pragma unroll
    for (int mt = 0; mt < 4; mt++) {
        int r0 = row0 + wm * 64 + mt * 16 + g;
        int r1 = r0 + 8;
#pragma unroll
        for (int nt = 0; nt < 4; nt++) {
            int cb = col0 + wn * 32 + nt * 8 + 2 * tg;
            if (r0 < M) {
                float v0 = fmaxf(c[mt][nt][0] + bl[nt][0], 0.f);
                float v1 = fmaxf(c[mt][nt][1] + bl[nt][1], 0.f);
                *(float2*)(g_h + (size_t)r0 * NC + cb) = make_float2(v0, v1);
                cs[nt][0] += v0; cq[nt][0] += v0 * v0;
                cs[nt][1] += v1; cq[nt][1] += v1 * v1;
            }
            if (r1 < M) {
                float v2 = fmaxf(c[mt][nt][2] + bl[nt][0], 0.f);
                float v3 = fmaxf(c[mt][nt][3] + bl[nt][1], 0.f);
                *(float2*)(g_h + (size_t)r1 * NC + cb) = make_float2(v2, v3);
                cs[nt][0] += v2; cq[nt][0] += v2 * v2;
                cs[nt][1] += v3; cq[nt][1] += v3 * v3;
            }
        }
    }

    // reduce over the g dimension (lanes sharing tg): xor masks 4, 8, 16
#pragma unroll
    for (int mask = 4; mask <= 16; mask <<= 1) {
#pragma unroll
        for (int nt = 0; nt < 4; nt++) {
            cs[nt][0] += __shfl_xor_sync(0xFFFFFFFFu, cs[nt][0], mask);
            cs[nt][1] += __shfl_xor_sync(0xFFFFFFFFu, cs[nt][1], mask);
            cq[nt][0] += __shfl_xor_sync(0xFFFFFFFFu, cq[nt][0], mask);
            cq[nt][1] += __shfl_xor_sync(0xFFFFFFFFu, cq[nt][1], mask);
        }
    }
    if (lane < 4) {   // lane == tg for these lanes
#pragma unroll
        for (int nt = 0; nt < 4; nt++) {
            int cc = wn * 32 + nt * 8 + 2 * lane;
            sm.ep.cs[wm][cc]     = cs[nt][0];
            sm.ep.cs[wm][cc + 1] = cs[nt][1];
            sm.ep.cq[wm][cc]     = cq[nt][0];
            sm.ep.cq[wm][cc + 1] = cq[nt][1];
        }
    }
    __syncthreads();
    if (tid < BN) {
        g_psum  [(size_t)mb * NC + col0 + tid] = sm.ep.cs[0][tid] + sm.ep.cs[1][tid];
        g_psumsq[(size_t)mb * NC + col0 + tid] = sm.ep.cq[0][tid] + sm.ep.cq[1][tid];
    }
}

// -------- column stats: coalesced, m-parallel; fold BN affine into (scale, shift) --------
__global__ void k_stats(const float* __restrict__ gamma, const float* __restrict__ beta,
                        int nbm, int NC, int N) {
    __shared__ float s_s[8][32];
    __shared__ float s_q[8][32];
    int txc = threadIdx.x;            // 0..31 column within group
    int tym = threadIdx.y;            // 0..7  m-parallel
    int c = blockIdx.x * 32 + txc;

    float s = 0.f, q = 0.f;
    for (int m = tym; m < nbm; m += 8) {
        s += g_psum  [(size_t)m * NC + c];
        q += g_psumsq[(size_t)m * NC + c];
    }
    s_s[tym][txc] = s;
    s_q[tym][txc] = q;
    __syncthreads();
    if (tym == 0) {
#pragma unroll
        for (int m = 1; m < 8; m++) { s += s_s[m][txc]; q += s_q[m][txc]; }
        float mu  = s / (float)N;
        float var = q / (float)N - mu * mu;
        float rstd = rsqrtf(var + 1e-5f);
        float sc = rstd * gamma[c];
        g_scale[c] = sc;
        g_shift[c] = beta[c] - mu * sc;
    }
}

// -------- BN apply (y = h*scale + shift) + row L2 normalize --------
__global__ void k_final(float* __restrict__ out, int N, int NC) {
    int i = blockIdx.x;
    int t = threadIdx.x;
    int lane = t & 31, warp = t >> 5;

    __shared__ float ws[8];
    __shared__ float s_rs;

    float4 y[4];          // NC=512, blockDim=128 -> exactly 4 float4 per thread
    int nchunk = 0;

    float ss = 0.f;
    for (int c = t * 4; c < NC; c += blockDim.x * 4) {
        float4 h  = *(const float4*)(g_h + (size_t)i * NC + c);
        float4 sc = *(const float4*)(g_scale + c);
        float4 sh = *(const float4*)(g_shift + c);
        float4 v;
        v.x = fmaf(h.x, sc.x, sh.x);
        v.y = fmaf(h.y, sc.y, sh.y);
        v.z = fmaf(h.z, sc.z, sh.z);
        v.w = fmaf(h.w, sc.w, sh.w);
        if (nchunk < 4) y[nchunk] = v;
        nchunk++;
        ss += v.x * v.x + v.y * v.y + v.z * v.z + v.w * v.w;
    }
#pragma unroll
    for (int off = 16; off > 0; off >>= 1)
        ss += __shfl_xor_sync(0xFFFFFFFFu, ss, off);
    if (lane == 0) ws[warp] = ss;
    __syncthreads();
    if (t == 0) {
        float tot = 0.f;
        int nw = (blockDim.x + 31) >> 5;
        for (int w = 0; w < nw; w++) tot += ws[w];
        s_rs = 1.f / (sqrtf(tot) + 1e-6f);
    }
    __syncthreads();
    float rs = s_rs;

    int idx = 0;
    for (int c = t * 4; c < NC && idx < 4; c += blockDim.x * 4, idx++) {
        float4 v = y[idx];
        v.x *= rs; v.y *= rs; v.z *= rs; v.w *= rs;
        *(float4*)(out + (size_t)i * NC + c) = v;
    }
}

extern "C" void kernel_launch(void* const* d_in, const int* in_sizes, int n_in,
                              void* d_out, int out_size) {
    const float* feat  = (const float*)d_in[0];
    const float* W     = (const float*)d_in[1];
    const float* bias  = (const float*)d_in[2];
    const float* gamma = (const float*)d_in[3];
    const float* beta  = (const float*)d_in[4];
    const void*  selfi = d_in[5];
    const void*  neigh = d_in[6];

    int D  = in_sizes[2];                       // 512
    long long NT = (long long)in_sizes[0] / D;  // 40000
    int K  = in_sizes[1] / D;                   // 1024 (= 2D)
    int N  = in_sizes[5];                       // 20000
    int S  = in_sizes[6] / N;                   // 25
    int nbm = (N + BM - 1) / BM;                // 157
    int wtotal = in_sizes[1];                   // 512*1024

    k_detect<<<1, 32>>>(neigh, (long long)in_sizes[6], NT);     // pos 0
    k_agg<<<N, 128>>>(feat, selfi, neigh, N, S, D);             // pos 1
    k_cvtw<<<(wtotal / 4 + 255) / 256, 256>>>(W, wtotal);       // pos 2 (also shifts ncu window)
    dim3 gg(nbm, D / BN);
    k_gemm<<<gg, 256>>>(bias, N, D, K);                         // pos 3 <- ncu capture slot
    dim3 sb(32, 8);
    k_stats<<<D / 32, sb>>>(gamma, beta, nbm, D, N);            // pos 4
    k_final<<<N, 128>>>((float*)d_out, N, D);                   // pos 5
}